// round 4
// baseline (speedup 1.0000x reference)
#include <cuda_runtime.h>
#include <cuda_bf16.h>

// q[i] = sum_j relu(neg[j] - pos[i] + DELTA)
//      = sum_j max(neg[j], t_i) - CHUNK * t_i   per chunk, with padding value
//        -3e38 contributing exactly t_i (cancelled by the CHUNK*t_i term).
// out[0..L)       = lambdas, then out[idx[i]] += mu*q[i]  (unique idx)
// out[out_size-1] = (mu/2 * q[P-1]^2 + lambdas[idx[P-1]] * q[P-1]) / (P*N)

#define ALM_DELTA 0.1f

static constexpr int MAX_P  = 4096;
static constexpr int JB_MAX = 96;
static constexpr int CHUNK  = 112;   // 28 float4 per chunk, compile-time trip count
static constexpr int IT     = 4;     // i-values per thread
static constexpr int BLK    = 128;   // threads per block

// Scratch (allocation-free rule: __device__ globals)
__device__ float g_qpart[JB_MAX * MAX_P];

// ---------------------------------------------------------------------------
// Kernel 1: pairwise partial sums. grid = (P/(BLK*IT), ceil(N/CHUNK)) = (8,74)
// = 592 CTAs = exactly 4 waves of 4 CTAs/SM (16 warps/SM).
// Fully-unrolled 28x float4 inner loop: 1 LDS.128 + 16 FMNMX + 16 FADD.
// jb==0 CTAs additionally copy lambdas -> out (independent of partials).
// ---------------------------------------------------------------------------
__global__ void __launch_bounds__(BLK, 4)
k_pairwise(const float* __restrict__ pos,
           const float* __restrict__ neg,
           const float* __restrict__ lambdas,
           float* __restrict__ out,
           int P, int N, int L, int iBlocks) {
    __shared__ __align__(16) float s_neg[CHUNK];

    const int jb = blockIdx.y;
    const int j0 = jb * CHUNK;
    for (int j = threadIdx.x; j < CHUNK; j += BLK) {
        const int gj = j0 + j;
        s_neg[j] = (gj < N) ? neg[gj] : -3.0e38f;   // pad -> contributes t exactly
    }
    __syncthreads();

    const int iBase = blockIdx.x * (BLK * IT) + threadIdx.x;

    float t[IT], accA[IT], accB[IT];
    #pragma unroll
    for (int k = 0; k < IT; ++k) {
        const int i = iBase + k * BLK;
        t[k]    = (i < P) ? (pos[i] - ALM_DELTA) : 0.f;
        accA[k] = 0.f;
        accB[k] = 0.f;
    }

    const float4* s4 = reinterpret_cast<const float4*>(s_neg);
    #pragma unroll
    for (int j = 0; j < CHUNK / 4; ++j) {
        const float4 v = s4[j];
        #pragma unroll
        for (int k = 0; k < IT; ++k) {
            accA[k] += fmaxf(v.x, t[k]);
            accB[k] += fmaxf(v.y, t[k]);
            accA[k] += fmaxf(v.z, t[k]);
            accB[k] += fmaxf(v.w, t[k]);
        }
    }

    #pragma unroll
    for (int k = 0; k < IT; ++k) {
        const int i = iBase + k * BLK;
        if (i < P)
            g_qpart[jb * P + i] = (accA[k] + accB[k]) - (float)CHUNK * t[k];
    }

    // lambdas -> out copy, amortized into the jb==0 CTAs (independent data).
    if (jb == 0) {
        const int stride = iBlocks * BLK;
        for (int l = blockIdx.x * BLK + threadIdx.x; l < L; l += stride)
            out[l] = lambdas[l];
    }
}

// ---------------------------------------------------------------------------
// Kernel 2 (fused epilogue): reduce partials -> q, scatter mu*q into out,
// write loss scalar. idx unique -> atomics hit disjoint addresses
// (deterministic). out already holds lambdas from kernel 1.
// ---------------------------------------------------------------------------
__global__ void k_epilogue(const int* __restrict__ idx,
                           const float* __restrict__ lambdas,
                           const float* __restrict__ mu,
                           float* __restrict__ out,
                           int P, int N, int L, int out_size, int jBlocks) {
    const int i = blockIdx.x * blockDim.x + threadIdx.x;
    if (i >= P) return;

    float s0 = 0.f, s1 = 0.f, s2 = 0.f, s3 = 0.f;
    int jb = 0;
    #pragma unroll 4
    for (; jb + 4 <= jBlocks; jb += 4) {     // independent loads: high MLP
        s0 += g_qpart[(jb + 0) * P + i];
        s1 += g_qpart[(jb + 1) * P + i];
        s2 += g_qpart[(jb + 2) * P + i];
        s3 += g_qpart[(jb + 3) * P + i];
    }
    for (; jb < jBlocks; ++jb)
        s0 += g_qpart[jb * P + i];
    const float q = (s0 + s1) + (s2 + s3);

    const float m = mu[0];
    atomicAdd(&out[idx[i]], m * q);

    if (i == P - 1 && out_size > L) {
        const float lam  = lambdas[idx[i]];  // pre-update lambda
        const float loss = (0.5f * m * q * q + lam * q) / ((float)P * (float)N);
        out[out_size - 1] = loss;
    }
}

extern "C" void kernel_launch(void* const* d_in, const int* in_sizes, int n_in,
                              void* d_out, int out_size) {
    const float* pos     = (const float*)d_in[0];   // buffer_batch_pos [P]
    const float* neg     = (const float*)d_in[1];   // buffer_batch_neg [N]
    const int*   idx     = (const int*)  d_in[2];   // lambdas_index_buffer [P]
    const float* lambdas = (const float*)d_in[3];   // lambdas [L]
    const float* mu      = (const float*)d_in[4];   // mu [1]
    float* out = (float*)d_out;

    const int P = in_sizes[0];
    const int N = in_sizes[1];
    const int L = in_sizes[3];

    const int iBlocks = (P + BLK * IT - 1) / (BLK * IT);   // 8 for P=4096
    const int jBlocks = (N + CHUNK - 1) / CHUNK;           // 74 for N=8192

    dim3 grid1(iBlocks, jBlocks);                          // 8 x 74 = 592
    k_pairwise<<<grid1, BLK>>>(pos, neg, lambdas, out, P, N, L, iBlocks);

    k_epilogue<<<(P + 127) / 128, 128>>>(idx, lambdas, mu, out,
                                         P, N, L, out_size, jBlocks);
}

// round 5
// speedup vs baseline: 1.2119x; 1.2119x over previous
#include <cuda_runtime.h>
#include <cuda_bf16.h>

// q[i] = sum_j relu(neg[j] - pos[i] + DELTA)
//      = sum_j max(neg[j], t_i) - CHUNK * t_i  per chunk (pad -3e38 -> adds t_i,
//        exactly cancelled by the CHUNK*t_i term).
// out[0..L)       = lambdas, then out[idx[i]] += mu*q[i]  (unique idx)
// out[out_size-1] = (mu/2 * q[P-1]^2 + lambdas[idx[P-1]] * q[P-1]) / (P*N)

#define ALM_DELTA 0.1f

static constexpr int MAX_P   = 4096;
static constexpr int QSTRIDE = 80;    // padded row stride (>= jBlocks=74)
static constexpr int CHUNK   = 112;   // 28 float4 per chunk, compile-time trips
static constexpr int IT      = 4;     // i-values per thread
static constexpr int BLK     = 128;   // threads per block (pairwise)

// Scratch (allocation-free rule: __device__ globals). Layout: [i][jb].
__device__ float g_qpart[MAX_P * QSTRIDE];

// ---------------------------------------------------------------------------
// Kernel 1: pairwise partial sums. grid = (8, 74) = 592 CTAs (4 waves of 4/SM).
// Fully-unrolled 28x float4 inner loop: 1 LDS.128 + 16 FMNMX + 16 FADD.
// Stores transposed (scattered, fire-and-forget) for a coalesced epilogue read.
// jb==0 CTAs also copy lambdas -> out (independent data).
// ---------------------------------------------------------------------------
__global__ void __launch_bounds__(BLK, 4)
k_pairwise(const float* __restrict__ pos,
           const float* __restrict__ neg,
           const float* __restrict__ lambdas,
           float* __restrict__ out,
           int P, int N, int L, int iBlocks) {
    __shared__ __align__(16) float s_neg[CHUNK];

    const int jb = blockIdx.y;
    const int j0 = jb * CHUNK;
    for (int j = threadIdx.x; j < CHUNK; j += BLK) {
        const int gj = j0 + j;
        s_neg[j] = (gj < N) ? neg[gj] : -3.0e38f;   // pad contributes exactly t
    }
    __syncthreads();

    const int iBase = blockIdx.x * (BLK * IT) + threadIdx.x;

    float t[IT], accA[IT], accB[IT];
    #pragma unroll
    for (int k = 0; k < IT; ++k) {
        const int i = iBase + k * BLK;
        t[k]    = (i < P) ? (pos[i] - ALM_DELTA) : 0.f;
        accA[k] = 0.f;
        accB[k] = 0.f;
    }

    const float4* s4 = reinterpret_cast<const float4*>(s_neg);
    #pragma unroll
    for (int j = 0; j < CHUNK / 4; ++j) {
        const float4 v = s4[j];
        #pragma unroll
        for (int k = 0; k < IT; ++k) {
            accA[k] += fmaxf(v.x, t[k]);
            accB[k] += fmaxf(v.y, t[k]);
            accA[k] += fmaxf(v.z, t[k]);
            accB[k] += fmaxf(v.w, t[k]);
        }
    }

    #pragma unroll
    for (int k = 0; k < IT; ++k) {
        const int i = iBase + k * BLK;
        if (i < P)
            g_qpart[i * QSTRIDE + jb] = (accA[k] + accB[k]) - (float)CHUNK * t[k];
    }

    // lambdas -> out copy, amortized into the jb==0 CTAs.
    if (jb == 0) {
        const int stride = iBlocks * BLK;
        for (int l = blockIdx.x * BLK + threadIdx.x; l < L; l += stride)
            out[l] = lambdas[l];
    }
}

// ---------------------------------------------------------------------------
// Kernel 2: warp-per-i reduction (coalesced row read), scatter, loss.
// 512 CTAs x 256 threads = 4096 warps; each lane loads <=3 partials -> shuffle
// reduce. Deterministic: fixed reduction order, unique scatter indices.
// ---------------------------------------------------------------------------
__global__ void __launch_bounds__(256)
k_epilogue(const int* __restrict__ idx,
           const float* __restrict__ lambdas,
           const float* __restrict__ mu,
           float* __restrict__ out,
           int P, int N, int L, int out_size, int jBlocks) {
    const int warpId = (blockIdx.x * blockDim.x + threadIdx.x) >> 5;
    const int lane   = threadIdx.x & 31;
    const int i      = warpId;
    if (i >= P) return;

    const float* row = &g_qpart[i * QSTRIDE];
    float s = 0.f;
    #pragma unroll
    for (int k = 0; k < 3; ++k) {           // covers jBlocks <= 96
        const int jb = lane + k * 32;
        if (jb < jBlocks) s += row[jb];
    }
    // warp tree-reduce (fixed order -> deterministic)
    #pragma unroll
    for (int off = 16; off > 0; off >>= 1)
        s += __shfl_xor_sync(0xFFFFFFFFu, s, off);

    if (lane == 0) {
        const float m = mu[0];
        atomicAdd(&out[idx[i]], m * s);
        if (i == P - 1 && out_size > L) {
            const float lam  = lambdas[idx[i]];   // pre-update lambda
            const float loss = (0.5f * m * s * s + lam * s) / ((float)P * (float)N);
            out[out_size - 1] = loss;
        }
    }
}

extern "C" void kernel_launch(void* const* d_in, const int* in_sizes, int n_in,
                              void* d_out, int out_size) {
    const float* pos     = (const float*)d_in[0];   // buffer_batch_pos [P]
    const float* neg     = (const float*)d_in[1];   // buffer_batch_neg [N]
    const int*   idx     = (const int*)  d_in[2];   // lambdas_index_buffer [P]
    const float* lambdas = (const float*)d_in[3];   // lambdas [L]
    const float* mu      = (const float*)d_in[4];   // mu [1]
    float* out = (float*)d_out;

    const int P = in_sizes[0];
    const int N = in_sizes[1];
    const int L = in_sizes[3];

    const int iBlocks = (P + BLK * IT - 1) / (BLK * IT);   // 8 for P=4096
    const int jBlocks = (N + CHUNK - 1) / CHUNK;           // 74 for N=8192

    dim3 grid1(iBlocks, jBlocks);                          // 8 x 74 = 592
    k_pairwise<<<grid1, BLK>>>(pos, neg, lambdas, out, P, N, L, iBlocks);

    const int warps  = P;                                  // one warp per i
    const int blocks = (warps * 32 + 255) / 256;           // 512 CTAs
    k_epilogue<<<blocks, 256>>>(idx, lambdas, mu, out, P, N, L, out_size, jBlocks);
}